// round 14
// baseline (speedup 1.0000x reference)
#include <cuda_runtime.h>
#include <cstdint>

// DeepInsightEncoding: out[b,h,w,c], c in {stamp, scatter, rowcopy, nd, bars}
// B=512, D=32, H=W=128. Output fp32 [512,128,128,5] = 168 MB -> HBM-write bound.
//
// R14: barrier-free (R12) + 2 rows/warp amortization (R13) WITHOUT the CTA-wide
// sync/drain that killed occupancy. 512 thr, 16 warps x 2 rows, 80 KB dynamic
// smem staging (2 CTAs/SM = full 2048 threads). Per-row 2560B TMA bulk store,
// one commit+wait per warp. rc/ndv shared across the row pair (h even).

#define THREADS 512
#define ROWS_PER_CTA 32
#define ROW_F4 160             // 128 px * 5 ch / 4 = 2560 B per row
#define SMEM_BYTES (ROWS_PER_CTA * 2560)
#define FULL 0xffffffffu

__global__ void __launch_bounds__(THREADS)
deepinsight_kernel(const float* __restrict__ inputs,   // [512,32]
                   const float* __restrict__ stamp,    // [128,128]
                   const int*   __restrict__ coords,   // [32,2]
                   float*       __restrict__ out)      // [512,128,128,5]
{
    extern __shared__ __align__(16) float4 stage[];    // 32 rows * 160 float4 = 80 KB

    const int b    = blockIdx.x >> 2;
    const int h0   = (blockIdx.x & 3) * ROWS_PER_CTA;
    const int warp = threadIdx.x >> 5;
    const int lane = threadIdx.x & 31;

    // ---- per-warp register prologue (once per 2 rows) ----
    const float v  = __ldg(inputs + b * 32 + lane);       // x[lane]
    const int2  cd = __ldg((const int2*)coords + lane);   // (row, col) for d=lane

    int bh = (int)rintf(v * 128.0f);                      // round-half-even == jnp.round
    bh = min(max(bh, 0), 128);

    float mn = v, mx = v;
    #pragma unroll
    for (int o = 16; o; o >>= 1) {
        mn = fminf(mn, __shfl_xor_sync(FULL, mn, o));
        mx = fmaxf(mx, __shfl_xor_sync(FULL, mx, o));
    }
    const float inv_range = 1.0f / (mx - mn);

    // bar columns: first at 17, stride 3, 32 bars (bar_w=1, gap=2, beg=15)
    int bi[4], bhk[4];
    #pragma unroll
    for (int k = 0; k < 4; k++) {
        int w = lane * 4 + k - 17;
        bi[k]  = (w >= 0 && w <= 93 && (w % 3) == 0) ? (w / 3) : -1;
        bhk[k] = __shfl_sync(FULL, bh, bi[k] < 0 ? 0 : bi[k]);
    }

    // rows hA (even) and hA+1 share hA>>2 -> same rc, same ndv
    const int   hA  = h0 + warp * 2;
    const float rc  = __shfl_sync(FULL, v, hA >> 2);
    const float ndv = fabsf(rc - v) * inv_range;          // cols 4*lane..+3

    #pragma unroll
    for (int rr = 0; rr < 2; rr++) {
        const int h = hA + rr;

        float bar[4];
        #pragma unroll
        for (int k = 0; k < 4; k++)
            bar[k] = (bi[k] >= 0 && h < bhk[k]) ? 1.0f : 0.0f;

        const float4 s4 = __ldg((const float4*)(stamp + h * 128 + lane * 4));

        // 20 floats -> staging (STS.128 @ 80B stride: conflict-free)
        float4* const stg = stage + (warp * 2 + rr) * ROW_F4;
        stg[lane * 5 + 0] = make_float4(s4.x,   0.0f,   rc,     ndv);
        stg[lane * 5 + 1] = make_float4(bar[0], s4.y,   0.0f,   rc);
        stg[lane * 5 + 2] = make_float4(ndv,    bar[1], s4.z,   0.0f);
        stg[lane * 5 + 3] = make_float4(rc,     ndv,    bar[2], s4.w);
        stg[lane * 5 + 4] = make_float4(0.0f,   rc,     ndv,    bar[3]);
        __syncwarp();

        // scatter patch: duplicates sum via atomicAdd (tf.scatter_nd)
        if (cd.x == h)
            atomicAdd(&((float*)stg)[cd.y * 5 + 1], v);
        __syncwarp();

        // drain this row: 2560B bulk store (async; tracked by final commit)
        if (lane == 0) {
            uint32_t saddr;
            asm volatile("{ .reg .u64 t; cvta.to.shared.u64 t, %1; cvt.u32.u64 %0, t; }"
                         : "=r"(saddr) : "l"(stg));
            float* gptr = out + (size_t)(b * 128 + h) * 640;
            asm volatile("fence.proxy.async.shared::cta;" ::: "memory");
            asm volatile("cp.async.bulk.global.shared::cta.bulk_group [%0], [%1], %2;"
                         :: "l"(gptr), "r"(saddr), "r"(2560u) : "memory");
        }
    }

    // one commit + one wait per warp (staging must outlive the TMA reads)
    if (lane == 0) {
        asm volatile("cp.async.bulk.commit_group;" ::: "memory");
        asm volatile("cp.async.bulk.wait_group.read 0;" ::: "memory");
    }
}

extern "C" void kernel_launch(void* const* d_in, const int* in_sizes, int n_in,
                              void* d_out, int out_size)
{
    const float* inputs = (const float*)d_in[0];   // [512,32]
    const float* stamp  = (const float*)d_in[1];   // [128,128,1]
    const int*   coords = (const int*)d_in[2];     // [32,2]
    float*       out    = (float*)d_out;           // [512,128,128,5]

    // 80 KB dynamic smem needs an opt-in (idempotent; safe under graph capture —
    // it is a function attribute, not a stream operation).
    cudaFuncSetAttribute(deepinsight_kernel,
                         cudaFuncAttributeMaxDynamicSharedMemorySize, SMEM_BYTES);

    deepinsight_kernel<<<512 * 4, THREADS, SMEM_BYTES>>>(inputs, stamp, coords, out);
}

// round 17
// speedup vs baseline: 1.4204x; 1.4204x over previous
#include <cuda_runtime.h>
#include <cstdint>

// DeepInsightEncoding: out[b,h,w,c], c in {stamp, scatter, rowcopy, nd, bars}
// B=512, D=32, H=W=128. Output fp32 [512,128,128,5] = 168 MB -> HBM-write bound.
//
// R15: R12 residency shape (512 thr, 16 warps, 40 KB static smem, 4 CTAs/SM,
// barrier-free) + 2 rows per warp by REUSING the same staging row:
//   fill row A -> TMA A -> compute row B regs (overlap) -> wait read A ->
//   fill row B -> TMA B -> wait.
// Prologue (LDGs, butterfly, bar tables) amortized over 2 rows; smem stays 40KB.

#define THREADS 512
#define NWARPS 16
#define ROW_F4 160             // 128 px * 5 ch / 4 = 2560 B per row
#define FULL 0xffffffffu

__global__ void __launch_bounds__(THREADS)
deepinsight_kernel(const float* __restrict__ inputs,   // [512,32]
                   const float* __restrict__ stamp,    // [128,128]
                   const int*   __restrict__ coords,   // [32,2]
                   float*       __restrict__ out)      // [512,128,128,5]
{
    __shared__ __align__(16) float4 stage[NWARPS][ROW_F4];  // 40 KB

    const int b    = blockIdx.x >> 2;
    const int h0   = (blockIdx.x & 3) * 32;     // CTA covers 32 rows, 2 per warp
    const int warp = threadIdx.x >> 5;
    const int lane = threadIdx.x & 31;

    // ---- per-warp register prologue (once per 2 rows) ----
    const float v  = __ldg(inputs + b * 32 + lane);       // x[lane]
    const int2  cd = __ldg((const int2*)coords + lane);   // (row, col) for d=lane

    int bh = (int)rintf(v * 128.0f);                      // round-half-even == jnp.round
    bh = min(max(bh, 0), 128);

    float mn = v, mx = v;
    #pragma unroll
    for (int o = 16; o; o >>= 1) {
        mn = fminf(mn, __shfl_xor_sync(FULL, mn, o));
        mx = fmaxf(mx, __shfl_xor_sync(FULL, mx, o));
    }
    const float inv_range = 1.0f / (mx - mn);

    // bar columns: first at 17, stride 3, 32 bars (bar_w=1, gap=2, beg=15)
    int bi[4], bhk[4];
    #pragma unroll
    for (int k = 0; k < 4; k++) {
        int w = lane * 4 + k - 17;
        bi[k]  = (w >= 0 && w <= 93 && (w % 3) == 0) ? (w / 3) : -1;
        bhk[k] = __shfl_sync(FULL, bh, bi[k] < 0 ? 0 : bi[k]);
    }

    float4* const stg  = stage[warp];
    float*  const stgF = (float*)stg;
    uint32_t saddr;
    asm volatile("{ .reg .u64 t; cvta.to.shared.u64 t, %1; cvt.u32.u64 %0, t; }"
                 : "=r"(saddr) : "l"(stg));

    #pragma unroll
    for (int p = 0; p < 2; p++) {
        const int h = h0 + p * 16 + warp;

        // per-row compute (scheduled before the inter-pass wait for overlap)
        const float rc  = __shfl_sync(FULL, v, h >> 2);        // rowcopy
        const float ndv = fabsf(rc - v) * inv_range;           // cols 4*lane..+3
        const float4 s4 = __ldg((const float4*)(stamp + h * 128 + lane * 4));
        float bar[4];
        #pragma unroll
        for (int k = 0; k < 4; k++)
            bar[k] = (bi[k] >= 0 && h < bhk[k]) ? 1.0f : 0.0f;

        if (p == 1) {
            // staging reuse: pass-0 TMA must have finished READING smem
            if (lane == 0)
                asm volatile("cp.async.bulk.wait_group.read 0;" ::: "memory");
            __syncwarp();
        }

        // 20 floats -> staging (STS.128 @ 80B stride: conflict-free)
        stg[lane * 5 + 0] = make_float4(s4.x,   0.0f,   rc,     ndv);
        stg[lane * 5 + 1] = make_float4(bar[0], s4.y,   0.0f,   rc);
        stg[lane * 5 + 2] = make_float4(ndv,    bar[1], s4.z,   0.0f);
        stg[lane * 5 + 3] = make_float4(rc,     ndv,    bar[2], s4.w);
        stg[lane * 5 + 4] = make_float4(0.0f,   rc,     ndv,    bar[3]);
        __syncwarp();

        // scatter patch: duplicates sum via atomicAdd (tf.scatter_nd)
        if (cd.x == h)
            atomicAdd(&stgF[cd.y * 5 + 1], v);
        __syncwarp();

        // drain this row: one 2560B TMA bulk store
        if (lane == 0) {
            float* gptr = out + (size_t)(b * 128 + h) * 640;   // 128*5 floats/row
            asm volatile("fence.proxy.async.shared::cta;" ::: "memory");
            asm volatile("cp.async.bulk.global.shared::cta.bulk_group [%0], [%1], %2;"
                         :: "l"(gptr), "r"(saddr), "r"(2560u) : "memory");
            asm volatile("cp.async.bulk.commit_group;" ::: "memory");
        }
    }

    // staging must outlive the final TMA read
    if (lane == 0)
        asm volatile("cp.async.bulk.wait_group.read 0;" ::: "memory");
}

extern "C" void kernel_launch(void* const* d_in, const int* in_sizes, int n_in,
                              void* d_out, int out_size)
{
    const float* inputs = (const float*)d_in[0];   // [512,32]
    const float* stamp  = (const float*)d_in[1];   // [128,128,1]
    const int*   coords = (const int*)d_in[2];     // [32,2]
    float*       out    = (float*)d_out;           // [512,128,128,5]

    deepinsight_kernel<<<512 * 4, THREADS>>>(inputs, stamp, coords, out);
}